// round 9
// baseline (speedup 1.0000x reference)
#include <cuda_runtime.h>
#include <cstdint>

// ---------------------------------------------------------------------------
// Problem constants
// ---------------------------------------------------------------------------
#define B_ROWS   16384
#define LCOLS    512
#define LP       514                     // L + 2
#define CAP      128                     // deferred-list capacity per warp

// Per-stream threefry constants with key-schedule adds prefolded (host-side).
struct StreamK {
    uint32_t i0, i1;                     // x0 = i0, x1 = c + i1
    uint32_t a1, b1, a2, b2, a3, b3, a4, b4, a5, b5;   // injection adds
};
struct GenParams {
    StreamK s[4][5];   // [channel][stream]; 0=data 1=mask 2=keep 3=ins 4=sym
};

// ---------------------------------------------------------------------------
// threefry2x32 (exact JAX schedule)
// ---------------------------------------------------------------------------
__host__ __device__ __forceinline__ uint32_t rotl32(uint32_t v, int r) {
#ifdef __CUDA_ARCH__
    return __funnelshift_l(v, v, r);
#else
    return (v << r) | (v >> (32 - r));
#endif
}

// Host-side reference tf2 (key-tree derivation only)
#define TF_ROUND_H(x0, x1, r) do { (x0) += (x1); (x1) = rotl32((x1), (r)); (x1) ^= (x0); } while (0)
static inline void h_tf2(uint32_t k0, uint32_t k1, uint32_t& x0, uint32_t& x1) {
    uint32_t k2 = k0 ^ k1 ^ 0x1BD11BDAu;
    x0 += k0; x1 += k1;
    TF_ROUND_H(x0,x1,13); TF_ROUND_H(x0,x1,15); TF_ROUND_H(x0,x1,26); TF_ROUND_H(x0,x1,6);
    x0 += k1; x1 += k2 + 1u;
    TF_ROUND_H(x0,x1,17); TF_ROUND_H(x0,x1,29); TF_ROUND_H(x0,x1,16); TF_ROUND_H(x0,x1,24);
    x0 += k2; x1 += k0 + 2u;
    TF_ROUND_H(x0,x1,13); TF_ROUND_H(x0,x1,15); TF_ROUND_H(x0,x1,26); TF_ROUND_H(x0,x1,6);
    x0 += k0; x1 += k1 + 3u;
    TF_ROUND_H(x0,x1,17); TF_ROUND_H(x0,x1,29); TF_ROUND_H(x0,x1,16); TF_ROUND_H(x0,x1,24);
    x0 += k1; x1 += k2 + 4u;
    TF_ROUND_H(x0,x1,13); TF_ROUND_H(x0,x1,15); TF_ROUND_H(x0,x1,26); TF_ROUND_H(x0,x1,6);
    x0 += k2; x1 += k0 + 5u;
}

// Force add onto the fma pipe (mad.lo with runtime multiplier `one` == 1).
__device__ __forceinline__ uint32_t imadd(uint32_t a, uint32_t one, uint32_t b) {
    uint32_t r;
    asm("mad.lo.u32 %0, %1, %2, %3;" : "=r"(r) : "r"(a), "r"(one), "r"(b));
    return r;
}

// Runtime rotate multipliers (1u << r), unfoldable by ptxas.
struct RotM { uint32_t m17, m29, m16, m24, m13, m15, m26, m6; };

// ALU-pipe round: SHF + LOP3
#define TFR_ALU(x0, x1, r) do { (x0) = imadd((x0), one, (x1)); (x1) = rotl32((x1), (r)) ^ (x0); } while (0)
// FMA-pipe round: rotl via 64-bit multiply (IMAD.WIDE) + one 3-input LOP3
#define TFR_FMA(x0, x1, M) do { \
    (x0) = imadd((x0), one, (x1)); \
    uint64_t _w = (uint64_t)(x1) * (uint64_t)(M); \
    (x1) = ((uint32_t)_w | (uint32_t)(_w >> 32)) ^ (x0); } while (0)

// Partitionable random_bits at counter (0, c): bits = o0 ^ o1.
// 8 of 20 rounds use the fma-pipe rotate to balance pipes.
__device__ __forceinline__ uint32_t pbits_f(const StreamK& s, uint32_t c,
                                            uint32_t one, const RotM& M) {
    uint32_t x0 = s.i0;
    uint32_t x1 = imadd(c, one, s.i1);
    TFR_ALU(x0,x1,13); TFR_ALU(x0,x1,15); TFR_ALU(x0,x1,26); TFR_ALU(x0,x1,6);
    x0 = imadd(x0, one, s.a1); x1 = imadd(x1, one, s.b1);
    TFR_FMA(x0,x1,M.m17); TFR_FMA(x0,x1,M.m29); TFR_FMA(x0,x1,M.m16); TFR_FMA(x0,x1,M.m24);
    x0 = imadd(x0, one, s.a2); x1 = imadd(x1, one, s.b2);
    TFR_FMA(x0,x1,M.m13); TFR_FMA(x0,x1,M.m15); TFR_FMA(x0,x1,M.m26); TFR_FMA(x0,x1,M.m6);
    x0 = imadd(x0, one, s.a3); x1 = imadd(x1, one, s.b3);
    TFR_ALU(x0,x1,17); TFR_ALU(x0,x1,29); TFR_ALU(x0,x1,16); TFR_ALU(x0,x1,24);
    x0 = imadd(x0, one, s.a4); x1 = imadd(x1, one, s.b4);
    TFR_ALU(x0,x1,13); TFR_ALU(x0,x1,15); TFR_ALU(x0,x1,26); TFR_ALU(x0,x1,6);
    x0 = imadd(x0, one, s.a5); x1 = imadd(x1, one, s.b5);
    return x0 ^ x1;
}

// ---------------------------------------------------------------------------
// Fused kernel: one warp per (row, channel); ch is block-uniform.
// Hot loop computes ONLY the 3 uniform streams (mask/keep/ins). Substituted
// values and inserted symbols (rare) are deferred to per-warp smem lists and
// drained 32-wide after the loop (~1 threefry block per list per row).
// Overflow (list > CAP) falls back to inline computation — always correct.
// ---------------------------------------------------------------------------
__global__ void __launch_bounds__(256) fused_kernel(GenParams P,
                                                    const float* __restrict__ x,
                                                    const float* __restrict__ p_sub,
                                                    const float* __restrict__ p_del,
                                                    const float* __restrict__ p_ins,
                                                    float* __restrict__ out,
                                                    uint32_t one) {
    __shared__ uint8_t  rowbuf[8][LCOLS];
    __shared__ uint32_t subl[8][CAP];
    __shared__ uint32_t insl[8][CAP];

    const uint32_t wib  = threadIdx.x >> 5;
    const uint32_t lane = threadIdx.x & 31u;
    const uint32_t ch   = blockIdx.x & 3u;                 // block-uniform
    const uint32_t b    = (blockIdx.x >> 2) * 8u + wib;    // 0..16383

    const uint32_t thr_sub9 = (uint32_t)ceilf(*p_sub * 8388608.0f) << 9;
    const uint32_t thr_del9 = (uint32_t)ceilf(*p_del * 8388608.0f) << 9;
    const uint32_t thr_ins9 = (uint32_t)ceilf(*p_ins * 8388608.0f) << 9;

    RotM M;
    M.m17 = one << 17; M.m29 = one << 29; M.m16 = one << 16; M.m24 = one << 24;
    M.m13 = one << 13; M.m15 = one << 15; M.m26 = one << 26; M.m6  = one << 6;

    const StreamK sd = P.s[ch][0];   // data (randint)       — deferred
    const StreamK sm = P.s[ch][1];   // sub mask (uniform)
    const StreamK sk = P.s[ch][2];   // del keep (uniform)
    const StreamK si = P.s[ch][3];   // ins flag (uniform)
    const StreamK ss = P.s[ch][4];   // ins sym (randint)    — deferred

    const float* xrow = x + (size_t)b * LCOLS;
    float*       orow = out + ((size_t)b * 4u + ch) * LP;
    uint8_t*     srow = rowbuf[wib];
    uint32_t*    swl  = subl[wib];
    uint32_t*    iwl  = insl[wib];

    const uint32_t lt = (1u << lane) - 1u;
    uint32_t srank = 0;   // survivors emitted so far
    uint32_t itot  = 0;   // insertions emitted so far
    uint32_t nsub  = 0;   // deferred substitution entries
    uint32_t nins  = 0;   // deferred insertion entries

    #pragma unroll 1
    for (int w = 0; w < LCOLS / 32; ++w) {
        if (srank + itot >= LP) break;     // all further emits would clip

        const uint32_t l  = (uint32_t)w * 32u + lane;
        const uint32_t i1 = b * LCOLS + l;   // (B,512) stream index
        const uint32_t i2 = b * LP + l;      // (B,514) stream index

        // ---- gen: 3 uniform streams only ----
        uint32_t mskb = pbits_f(sm, i1, one, M) < thr_sub9;
        uint32_t keep = pbits_f(sk, i1, one, M) >= thr_del9;
        uint32_t insf = pbits_f(si, i2, one, M) < thr_ins9;

        srow[l] = (uint8_t)insf;
        __syncwarp();

        // ---- scan ----
        int xi = (int)xrow[l];

        unsigned kmask = __ballot_sync(0xffffffffu, keep);
        int rank = __popc(kmask & lt);

        int insf2 = 0;
        if (keep) insf2 = srow[srank + (uint32_t)rank];      // survivor's flag
        unsigned imask = __ballot_sync(0xffffffffu, keep && insf2);

        uint32_t pos = srank + itot + (uint32_t)rank + (uint32_t)__popc(imask & lt);

        bool direct  = keep && pos < LP && !mskb;
        bool rec_sub = keep && pos < LP && mskb;
        bool rec_ins = keep && insf2 && (pos + 1) < LP;

        if (direct) orow[pos] = (float)(xi + 1);

        unsigned smask = __ballot_sync(0xffffffffu, rec_sub);
        if (smask) {
            int ns = __popc(smask);
            if (nsub + (uint32_t)ns <= CAP) {
                if (rec_sub)
                    swl[nsub + (uint32_t)__popc(smask & lt)] =
                        l | (pos << 9) | ((uint32_t)xi << 19);
                nsub += (uint32_t)ns;
            } else {  // overflow fallback: inline
                uint32_t dat = pbits_f(sd, i1, one, M) & 3u;
                if (rec_sub) orow[pos] = (float)((((uint32_t)xi + dat) & 3u) + 1u);
            }
        }

        unsigned rmask = __ballot_sync(0xffffffffu, rec_ins);
        if (rmask) {
            int ni = __popc(rmask);
            uint32_t j = srank + (uint32_t)rank;   // survivor index (< 512)
            if (nins + (uint32_t)ni <= CAP) {
                if (rec_ins)
                    iwl[nins + (uint32_t)__popc(rmask & lt)] = j | ((pos + 1) << 10);
                nins += (uint32_t)ni;
            } else {  // overflow fallback: inline
                uint32_t sym = pbits_f(ss, b * LP + j, one, M) & 3u;
                if (rec_ins) orow[pos + 1] = (float)(sym + 1u);
            }
        }

        srank += (uint32_t)__popc(kmask);
        itot  += (uint32_t)__popc(imask);
    }

    // tail = -1 padding, +1.0 => 0.0
    uint32_t cend = srank + itot;
    if (cend > LP) cend = LP;
    for (uint32_t j = cend + lane; j < LP; j += 32) orow[j] = 0.0f;

    // drain deferred substitutions (~10/row => usually 1 block)
    for (uint32_t t = lane; t < nsub; t += 32) {
        uint32_t e  = swl[t];
        uint32_t ll = e & 511u, pp = (e >> 9) & 1023u, xx = e >> 19;
        uint32_t dat = pbits_f(sd, b * LCOLS + ll, one, M) & 3u;
        orow[pp] = (float)(((xx + dat) & 3u) + 1u);
    }
    // drain deferred insertions (~5/row)
    for (uint32_t t = lane; t < nins; t += 32) {
        uint32_t e  = iwl[t];
        uint32_t jj = e & 1023u, pp = e >> 10;
        uint32_t sym = pbits_f(ss, b * LP + jj, one, M) & 3u;
        orow[pp] = (float)(sym + 1u);
    }
}

// ---------------------------------------------------------------------------
// Host: derive the full JAX key tree (partitionable / fold-like semantics:
// every derived key = threefry(parent, (0, index)) giving the (o0, o1) pair),
// then prefold each leaf key's injection schedule into StreamK.
// ---------------------------------------------------------------------------
static inline void h_key(uint32_t k0, uint32_t k1, uint32_t idx,
                         uint32_t& o0, uint32_t& o1) {
    uint32_t x0 = 0u, x1 = idx;
    h_tf2(k0, k1, x0, x1);
    o0 = x0; o1 = x1;
}

static inline StreamK make_stream(uint32_t k0, uint32_t k1) {
    uint32_t k2 = k0 ^ k1 ^ 0x1BD11BDAu;
    StreamK s;
    s.i0 = k0;        s.i1 = k1;
    s.a1 = k1;        s.b1 = k2 + 1u;
    s.a2 = k2;        s.b2 = k0 + 2u;
    s.a3 = k0;        s.b3 = k1 + 3u;
    s.a4 = k1;        s.b4 = k2 + 4u;
    s.a5 = k2;        s.b5 = k0 + 5u;
    return s;
}

extern "C" void kernel_launch(void* const* d_in, const int* in_sizes, int n_in,
                              void* d_out, int out_size) {
    const float* x     = (const float*)d_in[0];
    const float* p_sub = (const float*)d_in[1];
    const float* p_del = (const float*)d_in[2];
    const float* p_ins = (const float*)d_in[3];

    GenParams P;
    const uint32_t base0 = 0u, base1 = 42u;           // jax.random.key(42) -> (0, 42)
    for (uint32_t c = 0; c < 4; ++c) {
        uint32_t kc0, kc1;
        h_key(base0, base1, c, kc0, kc1);             // fold_in(key, c)

        // split(kc, 3) fold-like: key_i = tf(kc, (0, i))
        uint32_t k1_0, k1_1, k2_0, k2_1, k3_0, k3_1;
        h_key(kc0, kc1, 0u, k1_0, k1_1);              // sub key
        h_key(kc0, kc1, 1u, k2_0, k2_1);              // del key
        h_key(kc0, kc1, 2u, k3_0, k3_1);              // ins key

        // sub: split(k1, 2) -> data key (randint, internal split child 1),
        //                      mask key (uniform)
        uint32_t kd0, kd1, kdl0, kdl1, km0, km1;
        h_key(k1_0, k1_1, 0u, kd0, kd1);
        h_key(kd0, kd1, 1u, kdl0, kdl1);              // _randint lower_bits key
        h_key(k1_0, k1_1, 1u, km0, km1);

        // ins: split(k3, 2) -> flag key (uniform), sym key (randint child 1)
        uint32_t kf0, kf1, ks0, ks1, ksl0, ksl1;
        h_key(k3_0, k3_1, 0u, kf0, kf1);
        h_key(k3_0, k3_1, 1u, ks0, ks1);
        h_key(ks0, ks1, 1u, ksl0, ksl1);

        P.s[c][0] = make_stream(kdl0, kdl1);          // data
        P.s[c][1] = make_stream(km0, km1);            // sub mask
        P.s[c][2] = make_stream(k2_0, k2_1);          // del keep
        P.s[c][3] = make_stream(kf0, kf1);            // ins flag
        P.s[c][4] = make_stream(ksl0, ksl1);          // ins sym
    }

    // 65536 warps (one per row x channel) = 8192 blocks x 256 threads
    fused_kernel<<<8192, 256>>>(P, x, p_sub, p_del, p_ins, (float*)d_out, 1u);
}

// round 10
// speedup vs baseline: 1.0453x; 1.0453x over previous
#include <cuda_runtime.h>
#include <cstdint>

// ---------------------------------------------------------------------------
// Problem constants
// ---------------------------------------------------------------------------
#define B_ROWS   16384
#define LCOLS    512
#define LP       514                     // L + 2

// Per-stream threefry constants with key-schedule adds prefolded (host-side).
struct StreamK {
    uint32_t i0, i1;                     // x0 = i0, x1 = c + i1
    uint32_t a1, b1, a2, b2, a3, b3, a4, b4, a5, b5;   // injection adds
};
struct GenParams {
    StreamK s[4][5];   // [channel][stream]; 0=data 1=mask 2=keep 3=ins 4=sym
};

// ---------------------------------------------------------------------------
// threefry2x32 (exact JAX schedule)
// ---------------------------------------------------------------------------
__host__ __device__ __forceinline__ uint32_t rotl32(uint32_t v, int r) {
#ifdef __CUDA_ARCH__
    return __funnelshift_l(v, v, r);
#else
    return (v << r) | (v >> (32 - r));
#endif
}

// Host-side reference tf2 (key-tree derivation only)
#define TF_ROUND_H(x0, x1, r) do { (x0) += (x1); (x1) = rotl32((x1), (r)); (x1) ^= (x0); } while (0)
static inline void h_tf2(uint32_t k0, uint32_t k1, uint32_t& x0, uint32_t& x1) {
    uint32_t k2 = k0 ^ k1 ^ 0x1BD11BDAu;
    x0 += k0; x1 += k1;
    TF_ROUND_H(x0,x1,13); TF_ROUND_H(x0,x1,15); TF_ROUND_H(x0,x1,26); TF_ROUND_H(x0,x1,6);
    x0 += k1; x1 += k2 + 1u;
    TF_ROUND_H(x0,x1,17); TF_ROUND_H(x0,x1,29); TF_ROUND_H(x0,x1,16); TF_ROUND_H(x0,x1,24);
    x0 += k2; x1 += k0 + 2u;
    TF_ROUND_H(x0,x1,13); TF_ROUND_H(x0,x1,15); TF_ROUND_H(x0,x1,26); TF_ROUND_H(x0,x1,6);
    x0 += k0; x1 += k1 + 3u;
    TF_ROUND_H(x0,x1,17); TF_ROUND_H(x0,x1,29); TF_ROUND_H(x0,x1,16); TF_ROUND_H(x0,x1,24);
    x0 += k1; x1 += k2 + 4u;
    TF_ROUND_H(x0,x1,13); TF_ROUND_H(x0,x1,15); TF_ROUND_H(x0,x1,26); TF_ROUND_H(x0,x1,6);
    x0 += k2; x1 += k0 + 5u;
}

// Force add onto the fma pipe (mad.lo with runtime multiplier `one` == 1).
__device__ __forceinline__ uint32_t imadd(uint32_t a, uint32_t one, uint32_t b) {
    uint32_t r;
    asm("mad.lo.u32 %0, %1, %2, %3;" : "=r"(r) : "r"(a), "r"(one), "r"(b));
    return r;
}

// Runtime rotate multipliers (1u << r), unfoldable by ptxas.
struct RotM { uint32_t m17, m29, m16, m24; };

// ALU-pipe round: SHF + LOP3 (+ fma-pipe add)
#define TFR_ALU(x0, x1, r) do { (x0) = imadd((x0), one, (x1)); (x1) = rotl32((x1), (r)) ^ (x0); } while (0)
// FMA-pipe round: rotl via 64-bit multiply (IMAD.WIDE) + one 3-input LOP3
#define TFR_FMA(x0, x1, Mr) do { \
    (x0) = imadd((x0), one, (x1)); \
    uint64_t _w = (uint64_t)(x1) * (uint64_t)(Mr); \
    (x1) = ((uint32_t)_w | (uint32_t)(_w >> 32)) ^ (x0); } while (0)

// Partitionable random_bits at counter (0, c): bits = o0 ^ o1.
// 6 of 20 rounds use the fma-pipe rotate (alu 35 / fma 37 per block).
__device__ __forceinline__ uint32_t pbits_f(const StreamK& s, uint32_t c,
                                            uint32_t one, const RotM& M) {
    uint32_t x0 = s.i0;
    uint32_t x1 = imadd(c, one, s.i1);
    TFR_ALU(x0,x1,13); TFR_ALU(x0,x1,15); TFR_ALU(x0,x1,26); TFR_ALU(x0,x1,6);
    x0 = imadd(x0, one, s.a1); x1 = imadd(x1, one, s.b1);
    TFR_FMA(x0,x1,M.m17); TFR_FMA(x0,x1,M.m29); TFR_FMA(x0,x1,M.m16); TFR_FMA(x0,x1,M.m24);
    x0 = imadd(x0, one, s.a2); x1 = imadd(x1, one, s.b2);
    TFR_ALU(x0,x1,13); TFR_ALU(x0,x1,15); TFR_ALU(x0,x1,26); TFR_ALU(x0,x1,6);
    x0 = imadd(x0, one, s.a3); x1 = imadd(x1, one, s.b3);
    TFR_FMA(x0,x1,M.m17); TFR_FMA(x0,x1,M.m29); TFR_ALU(x0,x1,16); TFR_ALU(x0,x1,24);
    x0 = imadd(x0, one, s.a4); x1 = imadd(x1, one, s.b4);
    TFR_ALU(x0,x1,13); TFR_ALU(x0,x1,15); TFR_ALU(x0,x1,26); TFR_ALU(x0,x1,6);
    x0 = imadd(x0, one, s.a5); x1 = imadd(x1, one, s.b5);
    return x0 ^ x1;
}

// ---------------------------------------------------------------------------
// Fused kernel: one warp per (row, channel); ch is block-uniform.
// Per 32-elem chunk: 3 uniform threefry streams (mask@l, keep@l, and the
// ins-flag computed directly at SURVIVOR-RANK indices srank+lane — consumer
// fetches its flag with one shfl by rank; no smem, no syncwarp). Rare dat/sym
// blocks ballot-gated; sym also rank-indexed + shfl. Sequential-exact emit.
// ---------------------------------------------------------------------------
__global__ void __launch_bounds__(256) fused_kernel(GenParams P,
                                                    const float* __restrict__ x,
                                                    const float* __restrict__ p_sub,
                                                    const float* __restrict__ p_del,
                                                    const float* __restrict__ p_ins,
                                                    float* __restrict__ out,
                                                    uint32_t one) {
    const uint32_t wib  = threadIdx.x >> 5;
    const uint32_t lane = threadIdx.x & 31u;
    const uint32_t ch   = blockIdx.x & 3u;                 // block-uniform
    const uint32_t b    = (blockIdx.x >> 2) * 8u + wib;    // 0..16383

    const uint32_t thr_sub9 = (uint32_t)ceilf(*p_sub * 8388608.0f) << 9;
    const uint32_t thr_del9 = (uint32_t)ceilf(*p_del * 8388608.0f) << 9;
    const uint32_t thr_ins9 = (uint32_t)ceilf(*p_ins * 8388608.0f) << 9;

    RotM M;
    M.m17 = one << 17; M.m29 = one << 29; M.m16 = one << 16; M.m24 = one << 24;

    const StreamK sd = P.s[ch][0];   // data (randint)     — ballot-gated
    const StreamK sm = P.s[ch][1];   // sub mask (uniform)
    const StreamK sk = P.s[ch][2];   // del keep (uniform)
    const StreamK si = P.s[ch][3];   // ins flag (uniform) — rank-indexed
    const StreamK ss = P.s[ch][4];   // ins sym (randint)  — rank-indexed, gated

    const float* xrow = x + (size_t)b * LCOLS;
    float*       orow = out + ((size_t)b * 4u + ch) * LP;

    const uint32_t lt = (1u << lane) - 1u;
    uint32_t srank = 0;   // survivors emitted so far
    uint32_t itot  = 0;   // insertions emitted so far

    #pragma unroll 1
    for (int w = 0; w < LCOLS / 32; ++w) {
        if (srank + itot >= LP) break;       // all further emits would clip

        const uint32_t l  = (uint32_t)w * 32u + lane;
        const uint32_t i1 = b * LCOLS + l;           // (B,512) stream index
        const uint32_t ir = b * LP + srank + lane;   // rank-indexed (B,514)

        // ---- gen ----
        uint32_t mskb = pbits_f(sm, i1, one, M) < thr_sub9;
        uint32_t keep = pbits_f(sk, i1, one, M) >= thr_del9;
        uint32_t insf = pbits_f(si, ir, one, M) < thr_ins9;   // flag at rank srank+lane

        uint32_t dat = 0;
        if (__ballot_sync(0xffffffffu, mskb))
            dat = pbits_f(sd, i1, one, M) & 3u;

        // ---- scan ----
        int xi = (int)xrow[l];
        uint32_t val = ((uint32_t)xi + dat * mskb) & 3u;

        unsigned kmask = __ballot_sync(0xffffffffu, keep);
        int rank = __popc(kmask & lt);

        // survivor's ins flag: computed by lane `rank`
        uint32_t insf_r = __shfl_sync(0xffffffffu, insf, rank);
        bool myins = keep && insf_r;
        unsigned imask = __ballot_sync(0xffffffffu, myins);

        uint32_t pos = srank + itot + (uint32_t)rank + (uint32_t)__popc(imask & lt);

        uint32_t sym_r = 0;
        if (imask) {   // warp-uniform, taken ~27% of chunks
            uint32_t sym = pbits_f(ss, ir, one, M) & 3u;      // sym at rank srank+lane
            sym_r = __shfl_sync(0xffffffffu, sym, rank);
        }

        if (keep && pos < LP)          orow[pos]     = (float)(val + 1u);
        if (myins && pos + 1 < LP)     orow[pos + 1] = (float)(sym_r + 1u);

        srank += (uint32_t)__popc(kmask);
        itot  += (uint32_t)__popc(imask);
    }

    // tail = -1 padding, +1.0 => 0.0
    uint32_t cend = srank + itot;
    if (cend > LP) cend = LP;
    for (uint32_t j = cend + lane; j < LP; j += 32) orow[j] = 0.0f;
}

// ---------------------------------------------------------------------------
// Host: derive the full JAX key tree (partitionable / fold-like semantics:
// every derived key = threefry(parent, (0, index)) giving the (o0, o1) pair),
// then prefold each leaf key's injection schedule into StreamK.
// ---------------------------------------------------------------------------
static inline void h_key(uint32_t k0, uint32_t k1, uint32_t idx,
                         uint32_t& o0, uint32_t& o1) {
    uint32_t x0 = 0u, x1 = idx;
    h_tf2(k0, k1, x0, x1);
    o0 = x0; o1 = x1;
}

static inline StreamK make_stream(uint32_t k0, uint32_t k1) {
    uint32_t k2 = k0 ^ k1 ^ 0x1BD11BDAu;
    StreamK s;
    s.i0 = k0;        s.i1 = k1;
    s.a1 = k1;        s.b1 = k2 + 1u;
    s.a2 = k2;        s.b2 = k0 + 2u;
    s.a3 = k0;        s.b3 = k1 + 3u;
    s.a4 = k1;        s.b4 = k2 + 4u;
    s.a5 = k2;        s.b5 = k0 + 5u;
    return s;
}

extern "C" void kernel_launch(void* const* d_in, const int* in_sizes, int n_in,
                              void* d_out, int out_size) {
    const float* x     = (const float*)d_in[0];
    const float* p_sub = (const float*)d_in[1];
    const float* p_del = (const float*)d_in[2];
    const float* p_ins = (const float*)d_in[3];

    GenParams P;
    const uint32_t base0 = 0u, base1 = 42u;           // jax.random.key(42) -> (0, 42)
    for (uint32_t c = 0; c < 4; ++c) {
        uint32_t kc0, kc1;
        h_key(base0, base1, c, kc0, kc1);             // fold_in(key, c)

        // split(kc, 3) fold-like: key_i = tf(kc, (0, i))
        uint32_t k1_0, k1_1, k2_0, k2_1, k3_0, k3_1;
        h_key(kc0, kc1, 0u, k1_0, k1_1);              // sub key
        h_key(kc0, kc1, 1u, k2_0, k2_1);              // del key
        h_key(kc0, kc1, 2u, k3_0, k3_1);              // ins key

        // sub: split(k1, 2) -> data key (randint, internal split child 1),
        //                      mask key (uniform)
        uint32_t kd0, kd1, kdl0, kdl1, km0, km1;
        h_key(k1_0, k1_1, 0u, kd0, kd1);
        h_key(kd0, kd1, 1u, kdl0, kdl1);              // _randint lower_bits key
        h_key(k1_0, k1_1, 1u, km0, km1);

        // ins: split(k3, 2) -> flag key (uniform), sym key (randint child 1)
        uint32_t kf0, kf1, ks0, ks1, ksl0, ksl1;
        h_key(k3_0, k3_1, 0u, kf0, kf1);
        h_key(k3_0, k3_1, 1u, ks0, ks1);
        h_key(ks0, ks1, 1u, ksl0, ksl1);

        P.s[c][0] = make_stream(kdl0, kdl1);          // data
        P.s[c][1] = make_stream(km0, km1);            // sub mask
        P.s[c][2] = make_stream(k2_0, k2_1);          // del keep
        P.s[c][3] = make_stream(kf0, kf1);            // ins flag
        P.s[c][4] = make_stream(ksl0, ksl1);          // ins sym
    }

    // 65536 warps (one per row x channel) = 8192 blocks x 256 threads
    fused_kernel<<<8192, 256>>>(P, x, p_sub, p_del, p_ins, (float*)d_out, 1u);
}